// round 2
// baseline (speedup 1.0000x reference)
#include <cuda_runtime.h>
#include <math.h>

// ---------------- problem constants ----------------
#define T_STEPS 512
#define BATCH   64
#define IDIM    1024
#define HDIM    1024
#define G4      4096                 // 4*H
#define MTOT    (T_STEPS * BATCH)    // 32768

// ---------------- scratch ----------------
// x_gates stored as [4H][T*B] (row n = gate-row, col m = t*64+b)
__device__ float g_xg[(size_t)G4 * MTOT];   // 512 MB
__device__ unsigned g_ctr;                  // grid barrier counter

// =====================================================================
// Kernel 1: x_gates GEMM.  C[n][m] = sum_k Wih[n][k] * inp[m][k] + bias
// Classic 128x128x8 SGEMM, 256 threads, 8x8 micro-tile.
// =====================================================================
#define BM 128
#define BN 128
#define BK 8

__global__ void __launch_bounds__(256) xgates_kernel(
    const float* __restrict__ Wih,   // [4096][1024]
    const float* __restrict__ inp,   // [32768][1024]
    const float* __restrict__ bih,   // [4096]
    const float* __restrict__ bhh)   // [4096]
{
    __shared__ float As[BK][BM];   // W tile (n-major within k-slice)
    __shared__ float Bs[BK][BN];   // input tile (m-major within k-slice)

    const int tid = threadIdx.x;
    const int n0 = blockIdx.y * BM;      // gate-row tile
    const int m0 = blockIdx.x * BN;      // (t,b) tile

    const int lrow = tid >> 1;           // 0..127
    const int lk4  = (tid & 1) * 4;      // 0 or 4

    const float* Wg = Wih + (size_t)(n0 + lrow) * IDIM + lk4;
    const float* Ig = inp + (size_t)(m0 + lrow) * IDIM + lk4;

    const int tx = tid & 15;             // m micro-tile
    const int ty = tid >> 4;             // n micro-tile

    float acc[8][8];
#pragma unroll
    for (int i = 0; i < 8; ++i)
#pragma unroll
        for (int j = 0; j < 8; ++j) acc[i][j] = 0.f;

    for (int k0 = 0; k0 < IDIM; k0 += BK) {
        float4 wv = *(const float4*)(Wg + k0);
        float4 iv = *(const float4*)(Ig + k0);
        As[lk4 + 0][lrow] = wv.x; As[lk4 + 1][lrow] = wv.y;
        As[lk4 + 2][lrow] = wv.z; As[lk4 + 3][lrow] = wv.w;
        Bs[lk4 + 0][lrow] = iv.x; Bs[lk4 + 1][lrow] = iv.y;
        Bs[lk4 + 2][lrow] = iv.z; Bs[lk4 + 3][lrow] = iv.w;
        __syncthreads();

#pragma unroll
        for (int kk = 0; kk < BK; ++kk) {
            float a[8], b[8];
            *(float4*)&a[0] = *(const float4*)&As[kk][ty * 8];
            *(float4*)&a[4] = *(const float4*)&As[kk][ty * 8 + 4];
            *(float4*)&b[0] = *(const float4*)&Bs[kk][tx * 8];
            *(float4*)&b[4] = *(const float4*)&Bs[kk][tx * 8 + 4];
#pragma unroll
            for (int i = 0; i < 8; ++i)
#pragma unroll
                for (int j = 0; j < 8; ++j)
                    acc[i][j] += a[i] * b[j];
        }
        __syncthreads();
    }

    // epilogue: add bias (per n-row), store C[n][m], coalesced along m
#pragma unroll
    for (int i = 0; i < 8; ++i) {
        const int n = n0 + ty * 8 + i;
        const float bias = bih[n] + bhh[n];
        float* crow = g_xg + (size_t)n * MTOT + m0 + tx * 8;
        float4 v0, v1;
        v0.x = acc[i][0] + bias; v0.y = acc[i][1] + bias;
        v0.z = acc[i][2] + bias; v0.w = acc[i][3] + bias;
        v1.x = acc[i][4] + bias; v1.y = acc[i][5] + bias;
        v1.z = acc[i][6] + bias; v1.w = acc[i][7] + bias;
        *(float4*)(crow)     = v0;
        *(float4*)(crow + 4) = v1;
    }
}

// =====================================================================
// Kernel 2: persistent recurrent kernel, 128 CTAs, grid barrier per step
// CTA owns 8 hidden units -> 32 gate rows. W_hh slice cached in smem.
// =====================================================================
#define GC 128          // grid size (must all be co-resident)
#define WPAD 1025       // padded W row (bank-conflict-free)
#define HPAD 65         // padded h-tile row
#define GPAD 65         // padded gate staging row

// smem layout (floats):
//   Ws  [32][1025]  = 32800
//   Ht  [64][65]    =  4160
//   Gs  [32][65]    =  2080
//   Cs  [8][64]     =   512
//   Rs  [8]         =     8
#define SM_WS   0
#define SM_HT   (32 * WPAD)
#define SM_GS   (SM_HT + 64 * HPAD)
#define SM_CS   (SM_GS + 32 * GPAD)
#define SM_RS   (SM_CS + 8 * 64)
#define SM_FLOATS (SM_RS + 8)
#define SMEM_BYTES (SM_FLOATS * 4)

__global__ void reset_kernel() { g_ctr = 0u; }

__device__ __forceinline__ float sigf(float x) {
    return 1.f / (1.f + expf(-x));
}

__global__ void __launch_bounds__(256, 1) recurrent_kernel(
    const float* __restrict__ h0,
    const float* __restrict__ c0,
    const float* __restrict__ whh,   // [4096][1024]
    const float* __restrict__ retr,  // [1024]
    float* __restrict__ out)         // full d_out
{
    extern __shared__ float sm[];
    float* Ws = sm + SM_WS;
    float* Ht = sm + SM_HT;
    float* Gs = sm + SM_GS;
    float* Cs = sm + SM_CS;
    float* Rs = sm + SM_RS;

    const int tid = threadIdx.x;
    const int cta = blockIdx.x;
    const int j0  = cta * 8;        // hidden-unit slice base

    // ---- stage W_hh slice: rows r = g*8+u  <->  global row g*1024 + j0+u
    for (int idx = tid; idx < 32 * 256; idx += 256) {
        const int r  = idx >> 8;            // 0..31
        const int kq = (idx & 255) << 2;    // 0..1020
        const int g  = r >> 3, u = r & 7;
        const float4 v = *(const float4*)(whh + (size_t)(g * HDIM + j0 + u) * HDIM + kq);
        float* d = Ws + r * WPAD + kq;
        d[0] = v.x; d[1] = v.y; d[2] = v.z; d[3] = v.w;
    }
    if (tid < 8) Rs[tid] = retr[j0 + tid];
    for (int idx = tid; idx < 512; idx += 256) {
        const int u = idx & 7, b = idx >> 3;
        Cs[u * 64 + b] = c0[(size_t)b * HDIM + j0 + u];
    }
    __syncthreads();

    const int rg = tid >> 4;   // 0..15  (row-group: 2 rows)
    const int bg = tid & 15;   // 0..15  (batch-group: b = bg + 16*i)
    const int r0 = rg * 2;

    float* hT_out = out + (size_t)T_STEPS * BATCH * HDIM;
    float* cT_out = hT_out + (size_t)BATCH * HDIM;

    for (int t = 0; t < T_STEPS; ++t) {
        const float* hp = (t == 0) ? h0 : (out + (size_t)(t - 1) * BATCH * HDIM);

        float acc[2][4];
#pragma unroll
        for (int a = 0; a < 2; ++a)
#pragma unroll
            for (int b = 0; b < 4; ++b) acc[a][b] = 0.f;

        for (int kc = 0; kc < HDIM; kc += 64) {
            // load h chunk: Ht[b][k] (k within chunk), stride HPAD
#pragma unroll
            for (int rep = 0; rep < 4; ++rep) {
                const int idx = tid + rep * 256;
                const int b  = idx >> 4;
                const int kq = (idx & 15) << 2;
                const float4 v = *(const float4*)(hp + (size_t)b * HDIM + kc + kq);
                float* d = Ht + b * HPAD + kq;
                d[0] = v.x; d[1] = v.y; d[2] = v.z; d[3] = v.w;
            }
            __syncthreads();

            const float* w0p = Ws + r0 * WPAD + kc;
            const float* w1p = Ws + (r0 + 1) * WPAD + kc;
#pragma unroll 8
            for (int k = 0; k < 64; ++k) {
                const float w0 = w0p[k];
                const float w1 = w1p[k];
                const float h0v = Ht[(bg     ) * HPAD + k];
                const float h1v = Ht[(bg + 16) * HPAD + k];
                const float h2v = Ht[(bg + 32) * HPAD + k];
                const float h3v = Ht[(bg + 48) * HPAD + k];
                acc[0][0] += w0 * h0v; acc[0][1] += w0 * h1v;
                acc[0][2] += w0 * h2v; acc[0][3] += w0 * h3v;
                acc[1][0] += w1 * h0v; acc[1][1] += w1 * h1v;
                acc[1][2] += w1 * h2v; acc[1][3] += w1 * h3v;
            }
            __syncthreads();
        }

        // stage gates to smem
#pragma unroll
        for (int rr = 0; rr < 2; ++rr)
#pragma unroll
            for (int i = 0; i < 4; ++i)
                Gs[(r0 + rr) * GPAD + bg + 16 * i] = acc[rr][i];
        __syncthreads();

        // epilogue: 512 (u,b) cells, 2 per thread
        float* o_t = out + (size_t)t * BATCH * HDIM;
#pragma unroll
        for (int c2 = 0; c2 < 2; ++c2) {
            const int cell = tid + c2 * 256;
            const int u = cell & 7, b = cell >> 3;
            const size_t m = (size_t)t * BATCH + b;
            const int j = j0 + u;

            const float gi = Gs[(0 * 8 + u) * GPAD + b] + g_xg[(size_t)(0 * HDIM + j) * MTOT + m];
            const float gf = Gs[(1 * 8 + u) * GPAD + b] + g_xg[(size_t)(1 * HDIM + j) * MTOT + m];
            const float gg = Gs[(2 * 8 + u) * GPAD + b] + g_xg[(size_t)(2 * HDIM + j) * MTOT + m];
            const float go = Gs[(3 * 8 + u) * GPAD + b] + g_xg[(size_t)(3 * HDIM + j) * MTOT + m];

            const float c  = Cs[u * 64 + b];
            const float cy = sigf(gf) * c + sigf(gi) * tanhf(gg);
            float hy = sigf(go) * tanhf(cy);
            const float hpv = hp[(size_t)b * HDIM + j];
            const float rv  = Rs[u];
            hy = rv * hpv + (1.f - rv) * hy;

            Cs[u * 64 + b] = cy;
            o_t[(size_t)b * HDIM + j] = hy;
            if (t == T_STEPS - 1) {
                hT_out[(size_t)b * HDIM + j] = hy;
                cT_out[(size_t)b * HDIM + j] = cy;
            }
        }

        // ---- grid barrier ----
        __threadfence();
        __syncthreads();
        if (tid == 0) {
            atomicAdd(&g_ctr, 1u);
            const unsigned target = (unsigned)(t + 1) * GC;
            while (*(volatile unsigned*)&g_ctr < target) { }
        }
        __syncthreads();
    }
}

// =====================================================================
extern "C" void kernel_launch(void* const* d_in, const int* in_sizes, int n_in,
                              void* d_out, int out_size)
{
    const float* input_ = (const float*)d_in[0];
    const float* h0     = (const float*)d_in[1];
    const float* c0     = (const float*)d_in[2];
    const float* wih    = (const float*)d_in[3];
    const float* whh    = (const float*)d_in[4];
    const float* bih    = (const float*)d_in[5];
    const float* bhh    = (const float*)d_in[6];
    const float* retr   = (const float*)d_in[7];
    float* out = (float*)d_out;
    (void)in_sizes; (void)n_in; (void)out_size;

    cudaFuncSetAttribute(recurrent_kernel,
                         cudaFuncAttributeMaxDynamicSharedMemorySize, SMEM_BYTES);

    // x_gates GEMM: grid (m-tiles, n-tiles)
    xgates_kernel<<<dim3(MTOT / BN, G4 / BM), 256>>>(wih, input_, bih, bhh);

    // barrier counter reset (per launch, graph-replay safe)
    reset_kernel<<<1, 1>>>();

    // persistent recurrent kernel
    recurrent_kernel<<<GC, 256, SMEM_BYTES>>>(h0, c0, whh, retr, out);
}

// round 3
// speedup vs baseline: 1.2659x; 1.2659x over previous
#include <cuda_runtime.h>
#include <cuda_bf16.h>
#include <math.h>

#define T_STEPS 512
#define BATCH   64
#define IDIM    1024
#define HDIM    1024
#define G4      4096
#define MTOT    (T_STEPS * BATCH)

__device__ float g_xg[(size_t)G4 * MTOT];
__device__ unsigned g_ctr;

__device__ __forceinline__ unsigned smem_u32(const void* p) {
    return (unsigned)__cvta_generic_to_shared(p);
}

// =====================================================================
// Kernel 1: x_gates GEMM, tensor cores (bf16 hi/lo split, fp32 accum)
// C[n][m] = sum_k Wih[n][k]*inp[m][k] + bias_n ; CTA tile 128x128, BK=32
// =====================================================================
#define XSP   40                       // halves per smem row (32+8 pad)
#define XREG  (128 * XSP * 2)          // 10240 B per half-matrix region
#define XBUF  (4 * XREG)               // Whi,Wlo,Xhi,Xlo
#define XSMEM (2 * XBUF)               // 81920 B

#define LDM4(R0, R1, R2, R3, ADDR)                                           \
    asm volatile("ldmatrix.sync.aligned.m8n8.x4.shared.b16 {%0,%1,%2,%3},[%4];" \
                 : "=r"(R0), "=r"(R1), "=r"(R2), "=r"(R3) : "r"(ADDR))

#define MMA_BF16(D, A0, A1, A2, A3, B0, B1)                                  \
    asm volatile("mma.sync.aligned.m16n8k16.row.col.f32.bf16.bf16.f32 "      \
                 "{%0,%1,%2,%3},{%4,%5,%6,%7},{%8,%9},{%0,%1,%2,%3};"        \
                 : "+f"(D[0]), "+f"(D[1]), "+f"(D[2]), "+f"(D[3])            \
                 : "r"(A0), "r"(A1), "r"(A2), "r"(A3), "r"(B0), "r"(B1))

__device__ __forceinline__ unsigned pack_bf2(float a, float b) {
    __nv_bfloat162 t = __floats2bfloat162_rn(a, b);
    return *(unsigned*)&t;
}
__device__ __forceinline__ void split_store4(unsigned ahi, unsigned alo, float4 v) {
    float h0 = __bfloat162float(__float2bfloat16_rn(v.x));
    float h1 = __bfloat162float(__float2bfloat16_rn(v.y));
    float h2 = __bfloat162float(__float2bfloat16_rn(v.z));
    float h3 = __bfloat162float(__float2bfloat16_rn(v.w));
    unsigned p01 = pack_bf2(v.x, v.y), p23 = pack_bf2(v.z, v.w);
    unsigned l01 = pack_bf2(v.x - h0, v.y - h1), l23 = pack_bf2(v.z - h2, v.w - h3);
    asm volatile("st.shared.v2.u32 [%0], {%1,%2};" :: "r"(ahi), "r"(p01), "r"(p23));
    asm volatile("st.shared.v2.u32 [%0], {%1,%2};" :: "r"(alo), "r"(l01), "r"(l23));
}

__global__ void __launch_bounds__(256, 1) xgates_mma_kernel(
    const float* __restrict__ Wih, const float* __restrict__ inp,
    const float* __restrict__ bih, const float* __restrict__ bhh)
{
    extern __shared__ char xsm[];
    const unsigned sb = smem_u32(xsm);
    const int tid = threadIdx.x, lane = tid & 31, wid = tid >> 5;
    const int n0 = blockIdx.y * 128, m0 = blockIdx.x * 128;
    const int wn = (wid & 1) * 64, wm = (wid >> 1) * 32;

    float acc[4][4][4];
#pragma unroll
    for (int f = 0; f < 4; ++f)
#pragma unroll
        for (int q = 0; q < 4; ++q)
#pragma unroll
            for (int r = 0; r < 4; ++r) acc[f][q][r] = 0.f;

    unsigned offA[4], offB[2];
    {
        const int ar = wn + (lane & 15), ac = (lane >> 4) << 3;
#pragma unroll
        for (int f = 0; f < 4; ++f) offA[f] = (unsigned)(((ar + f * 16) * XSP + ac) * 2);
        const int br = wm + (lane & 7) + ((lane >> 4) << 3);
        const int bc = ((lane >> 3) & 1) << 3;
#pragma unroll
        for (int Q = 0; Q < 2; ++Q) offB[Q] = (unsigned)(((br + Q * 16) * XSP + bc) * 2);
    }

    float4 wreg[4], xreg[4];

#define LDG_CHUNK(C)                                                          \
    {   const float* Wp = Wih + (size_t)n0 * IDIM + (C) * 32;                 \
        const float* Xp = inp + (size_t)m0 * IDIM + (C) * 32;                 \
        _Pragma("unroll")                                                     \
        for (int i = 0; i < 4; ++i) {                                         \
            int idx = tid + i * 256, row = idx >> 3, g = idx & 7;             \
            wreg[i] = *(const float4*)(Wp + (size_t)row * IDIM + g * 4);      \
            xreg[i] = *(const float4*)(Xp + (size_t)row * IDIM + g * 4);      \
        } }

#define CVT_STS(BUF)                                                          \
    {   unsigned base = sb + (BUF) * XBUF;                                    \
        _Pragma("unroll")                                                     \
        for (int i = 0; i < 4; ++i) {                                         \
            int idx = tid + i * 256, row = idx >> 3, g = idx & 7;             \
            unsigned off = (unsigned)((row * XSP + g * 4) * 2);               \
            split_store4(base + off, base + XREG + off, wreg[i]);             \
            split_store4(base + 2 * XREG + off, base + 3 * XREG + off, xreg[i]); \
        } }

#define COMPUTE(BUF)                                                          \
    {   unsigned base = sb + (BUF) * XBUF;                                    \
        _Pragma("unroll")                                                     \
        for (int kk = 0; kk < 32; kk += 16) {                                 \
            unsigned kb = kk * 2;                                             \
            unsigned bh[4][2], bl[4][2];                                      \
            _Pragma("unroll")                                                 \
            for (int Q = 0; Q < 2; ++Q) {                                     \
                unsigned r0, r1, r2, r3;                                      \
                LDM4(r0, r1, r2, r3, base + 2 * XREG + offB[Q] + kb);         \
                bh[Q*2][0] = r0; bh[Q*2][1] = r1;                             \
                bh[Q*2+1][0] = r2; bh[Q*2+1][1] = r3;                         \
                LDM4(r0, r1, r2, r3, base + 3 * XREG + offB[Q] + kb);         \
                bl[Q*2][0] = r0; bl[Q*2][1] = r1;                             \
                bl[Q*2+1][0] = r2; bl[Q*2+1][1] = r3;                         \
            }                                                                 \
            _Pragma("unroll")                                                 \
            for (int f = 0; f < 4; ++f) {                                     \
                unsigned a0, a1, a2, a3, c0, c1, c2, c3;                      \
                LDM4(a0, a1, a2, a3, base + offA[f] + kb);                    \
                LDM4(c0, c1, c2, c3, base + XREG + offA[f] + kb);             \
                _Pragma("unroll")                                             \
                for (int q = 0; q < 4; ++q) {                                 \
                    MMA_BF16(acc[f][q], a0, a1, a2, a3, bh[q][0], bh[q][1]);  \
                    MMA_BF16(acc[f][q], a0, a1, a2, a3, bl[q][0], bl[q][1]);  \
                    MMA_BF16(acc[f][q], c0, c1, c2, c3, bh[q][0], bh[q][1]);  \
                } } } }

    LDG_CHUNK(0); CVT_STS(0); __syncthreads();
    for (int c = 0; c < 32; ++c) {
        if (c < 31) LDG_CHUNK(c + 1);
        COMPUTE(c & 1);
        __syncthreads();
        if (c < 31) CVT_STS((c + 1) & 1);
        __syncthreads();
    }

    const int erow = lane >> 2, ecol = (lane & 3) * 2;
#pragma unroll
    for (int f = 0; f < 4; ++f) {
        const int n = n0 + wn + f * 16 + erow;
        const float b0 = bih[n] + bhh[n];
        const float b8 = bih[n + 8] + bhh[n + 8];
#pragma unroll
        for (int q = 0; q < 4; ++q) {
            const int m = m0 + wm + q * 8 + ecol;
            *(float2*)(g_xg + (size_t)n * MTOT + m) =
                make_float2(acc[f][q][0] + b0, acc[f][q][1] + b0);
            *(float2*)(g_xg + (size_t)(n + 8) * MTOT + m) =
                make_float2(acc[f][q][2] + b8, acc[f][q][3] + b8);
        }
    }
#undef LDG_CHUNK
#undef CVT_STS
#undef COMPUTE
}

// =====================================================================
// Kernel 2: persistent recurrent kernel (unchanged from R1, known-good)
// =====================================================================
#define GC 128
#define WPAD 1025
#define HPAD 65
#define GPAD 65
#define SM_WS   0
#define SM_HT   (32 * WPAD)
#define SM_GS   (SM_HT + 64 * HPAD)
#define SM_CS   (SM_GS + 32 * GPAD)
#define SM_RS   (SM_CS + 8 * 64)
#define SMEM_BYTES ((SM_RS + 8) * 4)

__global__ void reset_kernel() { g_ctr = 0u; }

__device__ __forceinline__ float sigf(float x) { return 1.f / (1.f + expf(-x)); }

__global__ void __launch_bounds__(256, 1) recurrent_kernel(
    const float* __restrict__ h0, const float* __restrict__ c0,
    const float* __restrict__ whh, const float* __restrict__ retr,
    float* __restrict__ out)
{
    extern __shared__ float sm[];
    float* Ws = sm + SM_WS;
    float* Ht = sm + SM_HT;
    float* Gs = sm + SM_GS;
    float* Cs = sm + SM_CS;
    float* Rs = sm + SM_RS;

    const int tid = threadIdx.x;
    const int j0 = blockIdx.x * 8;

    for (int idx = tid; idx < 32 * 256; idx += 256) {
        const int r = idx >> 8, kq = (idx & 255) << 2;
        const int g = r >> 3, u = r & 7;
        const float4 v = *(const float4*)(whh + (size_t)(g * HDIM + j0 + u) * HDIM + kq);
        float* d = Ws + r * WPAD + kq;
        d[0] = v.x; d[1] = v.y; d[2] = v.z; d[3] = v.w;
    }
    if (tid < 8) Rs[tid] = retr[j0 + tid];
    for (int idx = tid; idx < 512; idx += 256) {
        const int u = idx & 7, b = idx >> 3;
        Cs[u * 64 + b] = c0[(size_t)b * HDIM + j0 + u];
    }
    __syncthreads();

    const int rg = tid >> 4, bg = tid & 15, r0 = rg * 2;
    float* hT_out = out + (size_t)T_STEPS * BATCH * HDIM;
    float* cT_out = hT_out + (size_t)BATCH * HDIM;

    for (int t = 0; t < T_STEPS; ++t) {
        const float* hp = (t == 0) ? h0 : (out + (size_t)(t - 1) * BATCH * HDIM);

        float acc[2][4];
#pragma unroll
        for (int a = 0; a < 2; ++a)
#pragma unroll
            for (int b = 0; b < 4; ++b) acc[a][b] = 0.f;

        for (int kc = 0; kc < HDIM; kc += 64) {
#pragma unroll
            for (int rep = 0; rep < 4; ++rep) {
                const int idx = tid + rep * 256;
                const int b = idx >> 4, kq = (idx & 15) << 2;
                const float4 v = *(const float4*)(hp + (size_t)b * HDIM + kc + kq);
                float* d = Ht + b * HPAD + kq;
                d[0] = v.x; d[1] = v.y; d[2] = v.z; d[3] = v.w;
            }
            __syncthreads();

            const float* w0p = Ws + r0 * WPAD + kc;
            const float* w1p = Ws + (r0 + 1) * WPAD + kc;
#pragma unroll 8
            for (int k = 0; k < 64; ++k) {
                const float w0 = w0p[k], w1 = w1p[k];
                const float h0v = Ht[(bg     ) * HPAD + k];
                const float h1v = Ht[(bg + 16) * HPAD + k];
                const float h2v = Ht[(bg + 32) * HPAD + k];
                const float h3v = Ht[(bg + 48) * HPAD + k];
                acc[0][0] += w0 * h0v; acc[0][1] += w0 * h1v;
                acc[0][2] += w0 * h2v; acc[0][3] += w0 * h3v;
                acc[1][0] += w1 * h0v; acc[1][1] += w1 * h1v;
                acc[1][2] += w1 * h2v; acc[1][3] += w1 * h3v;
            }
            __syncthreads();
        }

#pragma unroll
        for (int rr = 0; rr < 2; ++rr)
#pragma unroll
            for (int i = 0; i < 4; ++i)
                Gs[(r0 + rr) * GPAD + bg + 16 * i] = acc[rr][i];
        __syncthreads();

        float* o_t = out + (size_t)t * BATCH * HDIM;
#pragma unroll
        for (int c2 = 0; c2 < 2; ++c2) {
            const int cell = tid + c2 * 256;
            const int u = cell & 7, b = cell >> 3;
            const size_t m = (size_t)t * BATCH + b;
            const int j = j0 + u;

            const float gi = Gs[(0 * 8 + u) * GPAD + b] + g_xg[(size_t)(0 * HDIM + j) * MTOT + m];
            const float gf = Gs[(1 * 8 + u) * GPAD + b] + g_xg[(size_t)(1 * HDIM + j) * MTOT + m];
            const float gg = Gs[(2 * 8 + u) * GPAD + b] + g_xg[(size_t)(2 * HDIM + j) * MTOT + m];
            const float go = Gs[(3 * 8 + u) * GPAD + b] + g_xg[(size_t)(3 * HDIM + j) * MTOT + m];

            const float c = Cs[u * 64 + b];
            const float cy = sigf(gf) * c + sigf(gi) * tanhf(gg);
            float hy = sigf(go) * tanhf(cy);
            const float hpv = hp[(size_t)b * HDIM + j];
            const float rv = Rs[u];
            hy = rv * hpv + (1.f - rv) * hy;

            Cs[u * 64 + b] = cy;
            o_t[(size_t)b * HDIM + j] = hy;
            if (t == T_STEPS - 1) {
                hT_out[(size_t)b * HDIM + j] = hy;
                cT_out[(size_t)b * HDIM + j] = cy;
            }
        }

        __threadfence();
        __syncthreads();
        if (tid == 0) {
            atomicAdd(&g_ctr, 1u);
            const unsigned target = (unsigned)(t + 1) * GC;
            while (*(volatile unsigned*)&g_ctr < target) { }
        }
        __syncthreads();
    }
}

// =====================================================================
extern "C" void kernel_launch(void* const* d_in, const int* in_sizes, int n_in,
                              void* d_out, int out_size)
{
    const float* input_ = (const float*)d_in[0];
    const float* h0     = (const float*)d_in[1];
    const float* c0     = (const float*)d_in[2];
    const float* wih    = (const float*)d_in[3];
    const float* whh    = (const float*)d_in[4];
    const float* bih    = (const float*)d_in[5];
    const float* bhh    = (const float*)d_in[6];
    const float* retr   = (const float*)d_in[7];
    float* out = (float*)d_out;
    (void)in_sizes; (void)n_in; (void)out_size;

    cudaFuncSetAttribute(xgates_mma_kernel,
                         cudaFuncAttributeMaxDynamicSharedMemorySize, XSMEM);
    cudaFuncSetAttribute(recurrent_kernel,
                         cudaFuncAttributeMaxDynamicSharedMemorySize, SMEM_BYTES);

    xgates_mma_kernel<<<dim3(MTOT / 128, G4 / 128), 256, XSMEM>>>(wih, input_, bih, bhh);
    reset_kernel<<<1, 1>>>();
    recurrent_kernel<<<GC, 256, SMEM_BYTES>>>(h0, c0, whh, retr, out);
}